// round 13
// baseline (speedup 1.0000x reference)
#include <cuda_runtime.h>
#include <cuda_bf16.h>
#include <math.h>
#include <stdint.h>

#define BB 4096
#define DD 1024

#define THRESH   0.5f
#define MARGIN   0.1f
#define SCALE_P  2.0f
#define SCALE_N  40.0f
#define EPS      1e-5f

#define SQ       640.0f
#define INV_SQ2  (1.0f / (SQ * SQ))

// Static scratch (no allocs): sim fp32 (64MB), int8 x (4MB), labels, row losses.
__device__ float g_sim[(size_t)BB * BB];
__device__ __align__(16) signed char g_xq[(size_t)BB * DD];
__device__ __align__(16) unsigned char g_lab8[BB];
__device__ float g_rowloss[BB];
__device__ int g_ctr = 0;

// ---------------------------------------------------------------------------
// Helpers
// ---------------------------------------------------------------------------
__device__ __forceinline__ uint32_t smem_u32(const void* p) {
    uint32_t a;
    asm("{ .reg .u64 t; cvta.to.shared.u64 t, %1; cvt.u32.u64 %0, t; }"
        : "=r"(a) : "l"(p));
    return a;
}
#define CP_ASYNC16(dst, src) \
    asm volatile("cp.async.cg.shared.global [%0], [%1], 16;" :: "r"(dst), "l"(src))
#define CP_COMMIT() asm volatile("cp.async.commit_group;" ::: "memory")
#define CP_WAIT(n)  asm volatile("cp.async.wait_group %0;" :: "n"(n) : "memory")

__device__ __forceinline__ void ldmatrix_x4(uint32_t& r0, uint32_t& r1,
                                            uint32_t& r2, uint32_t& r3,
                                            uint32_t addr) {
    asm volatile("ldmatrix.sync.aligned.m8n8.x4.shared.b16 {%0,%1,%2,%3}, [%4];"
                 : "=r"(r0), "=r"(r1), "=r"(r2), "=r"(r3) : "r"(addr));
}
__device__ __forceinline__ void mma_s8(int& c0, int& c1, int& c2, int& c3,
                                       uint32_t a0, uint32_t a1, uint32_t a2,
                                       uint32_t a3, uint32_t b0, uint32_t b1) {
    asm volatile(
        "mma.sync.aligned.m16n8k32.row.col.s32.s8.s8.s32 "
        "{%0,%1,%2,%3}, {%4,%5,%6,%7}, {%8,%9}, {%0,%1,%2,%3};"
        : "+r"(c0), "+r"(c1), "+r"(c2), "+r"(c3)
        : "r"(a0), "r"(a1), "r"(a2), "r"(a3), "r"(b0), "r"(b1));
}

// ---------------------------------------------------------------------------
// Pass 0: f32 -> int8 quantization of x (scale SQ) + labels -> u8 (block 0).
// ---------------------------------------------------------------------------
__device__ __forceinline__ uint32_t q4(float a, float b, float c, float d) {
    const int qa = __float2int_rn(fminf(fmaxf(a * SQ, -127.f), 127.f));
    const int qb = __float2int_rn(fminf(fmaxf(b * SQ, -127.f), 127.f));
    const int qc = __float2int_rn(fminf(fmaxf(c * SQ, -127.f), 127.f));
    const int qd = __float2int_rn(fminf(fmaxf(d * SQ, -127.f), 127.f));
    return (uint32_t)(qa & 255) | ((uint32_t)(qb & 255) << 8) |
           ((uint32_t)(qc & 255) << 16) | ((uint32_t)(qd & 255) << 24);
}

__global__ __launch_bounds__(256) void convert_q8(const float4* __restrict__ x,
                                                  const int* __restrict__ labels) {
    const int i = blockIdx.x * 256 + threadIdx.x;   // over 512K uint2 outputs
    const float4 v0 = x[i * 2];
    const float4 v1 = x[i * 2 + 1];
    uint2 w;
    w.x = q4(v0.x, v0.y, v0.z, v0.w);
    w.y = q4(v1.x, v1.y, v1.z, v1.w);
    ((uint2*)g_xq)[i] = w;

    if (blockIdx.x == 0) {
        const int t = threadIdx.x;      // 16 labels each
#pragma unroll
        for (int k = 0; k < 4; k++) {
            int4 lv = *(const int4*)(labels + t * 16 + k * 4);
            uchar4 u;
            u.x = (unsigned char)lv.x; u.y = (unsigned char)lv.y;
            u.z = (unsigned char)lv.z; u.w = (unsigned char)lv.w;
            *(uchar4*)(g_lab8 + t * 16 + k * 4) = u;
        }
    }
}

// ---------------------------------------------------------------------------
// Pass 1: int8 IMMA symmetric GEMM (exact s32 accumulate, scale at epilogue).
// Triangular 528-CTA launch, tile 128x128, 8 warps (2x4), warp tile 64x32,
// K-chunk 128 bytes, 2-stage cp.async, single sync per chunk.
// ---------------------------------------------------------------------------
#define KCB 128                     // K bytes per chunk
#define NCHUNK (DD / KCB)           // 8
#define ROWB 144                    // 128 data + 16 pad
#define TILE_B (128 * ROWB)         // 18432 B per A or B stage
#define OFF_B  (2 * TILE_B)
#define SMEM_DYN (4 * TILE_B)       // 73728 B
#define NT 32
#define NCTA (NT * (NT + 1) / 2)    // 528

__global__ __launch_bounds__(256, 2) void sim_gemm_imma() {
    // Triangular decode: idx -> (bi, bj), bi <= bj.
    const int idx = blockIdx.x;
    int bi = (int)((65.0f - sqrtf(4225.0f - 8.0f * (float)idx)) * 0.5f);
    while ((bi + 1) * (65 - (bi + 1)) / 2 <= idx) bi++;
    while (bi * (65 - bi) / 2 > idx) bi--;
    const int bj = bi + (idx - bi * (65 - bi) / 2);

    extern __shared__ __align__(16) char smem[];
    const uint32_t sA = smem_u32(smem);
    const uint32_t sB = sA + OFF_B;

    const int tid = threadIdx.x;
    const int wid = tid >> 5, lane = tid & 31;
    const int warp_m = wid >> 2;
    const int warp_n = wid & 3;
    const int row0 = bi * 128, col0 = bj * 128;

    uint32_t dstA[4];
    const signed char *srcA[4], *srcB[4];
#pragma unroll
    for (int p = 0; p < 4; p++) {
        const int ii = p * 256 + tid;
        const int r = ii >> 3, kc = ii & 7;      // 8 x 16B = 128B row
        dstA[p] = (uint32_t)(r * ROWB + kc * 16);
        srcA[p] = g_xq + (size_t)(row0 + r) * DD + kc * 16;
        srcB[p] = g_xq + (size_t)(col0 + r) * DD + kc * 16;
    }

    int acc[4][4][4];
#pragma unroll
    for (int a = 0; a < 4; a++)
#pragma unroll
        for (int b = 0; b < 4; b++)
#pragma unroll
            for (int c = 0; c < 4; c++) acc[a][b][c] = 0;

    // ldmatrix lane addressing (bytes; identical bit pattern to bf16 case).
    const int a_mrow = warp_m * 64 + (lane & 7) + ((lane >> 3) & 1) * 8;
    const int a_kb   = ((lane >> 4) & 1) * 16;
    const int b_nrow = warp_n * 32 + (lane & 7) + ((lane >> 4) << 3);
    const int b_kb   = ((lane >> 3) & 1) * 16;

    // Prologue: chunk 0 -> stage 0.
#pragma unroll
    for (int p = 0; p < 4; p++) {
        CP_ASYNC16(sA + dstA[p], srcA[p]);
        CP_ASYNC16(sB + dstA[p], srcB[p]);
    }
    CP_COMMIT();

    for (int ck = 0; ck < NCHUNK; ck++) {
        CP_WAIT(0);
        __syncthreads();

        if (ck + 1 < NCHUNK) {
            const uint32_t st = ((ck + 1) & 1) * TILE_B;
            const int k0 = (ck + 1) * KCB;
#pragma unroll
            for (int p = 0; p < 4; p++) {
                CP_ASYNC16(sA + st + dstA[p], srcA[p] + k0);
                CP_ASYNC16(sB + st + dstA[p], srcB[p] + k0);
            }
            CP_COMMIT();
        }

        const uint32_t stA = sA + (ck & 1) * TILE_B;
        const uint32_t stB = sB + (ck & 1) * TILE_B;

#pragma unroll
        for (int ks = 0; ks < KCB / 32; ks++) {   // 4 k-steps of 32 bytes
            uint32_t af[4][4], bf[2][4];
#pragma unroll
            for (int mf = 0; mf < 4; mf++)
                ldmatrix_x4(af[mf][0], af[mf][1], af[mf][2], af[mf][3],
                            stA + (uint32_t)((a_mrow + mf * 16) * ROWB
                                             + ks * 32 + a_kb));
#pragma unroll
            for (int nfp = 0; nfp < 2; nfp++)
                ldmatrix_x4(bf[nfp][0], bf[nfp][1], bf[nfp][2], bf[nfp][3],
                            stB + (uint32_t)((b_nrow + nfp * 16) * ROWB
                                             + ks * 32 + b_kb));
#pragma unroll
            for (int mf = 0; mf < 4; mf++)
#pragma unroll
                for (int nf = 0; nf < 4; nf++) {
                    const uint32_t b0 = bf[nf >> 1][(nf & 1) * 2];
                    const uint32_t b1 = bf[nf >> 1][(nf & 1) * 2 + 1];
                    mma_s8(acc[mf][nf][0], acc[mf][nf][1],
                           acc[mf][nf][2], acc[mf][nf][3],
                           af[mf][0], af[mf][1], af[mf][2], af[mf][3], b0, b1);
                }
        }
    }
    __syncthreads();   // all reads done before smem reuse

    // Epilogue: scale to float -> padded SMEM (stride 129) -> global (+mirror).
    float* smf = (float*)smem;
    {
        const int r_lo = warp_m * 64 + (lane >> 2);
        const int c_lo = warp_n * 32 + (lane & 3) * 2;
#pragma unroll
        for (int mf = 0; mf < 4; mf++)
#pragma unroll
            for (int nf = 0; nf < 4; nf++) {
                const int r = r_lo + mf * 16;
                const int c = c_lo + nf * 8;
                smf[r * 129 + c]           = (float)acc[mf][nf][0] * INV_SQ2;
                smf[r * 129 + c + 1]       = (float)acc[mf][nf][1] * INV_SQ2;
                smf[(r + 8) * 129 + c]     = (float)acc[mf][nf][2] * INV_SQ2;
                smf[(r + 8) * 129 + c + 1] = (float)acc[mf][nf][3] * INV_SQ2;
            }
    }
    __syncthreads();

    const int cc = tid & 127;
    const int rh = tid >> 7;
#pragma unroll 4
    for (int i = 0; i < 64; i++) {
        const int r = i * 2 + rh;
        g_sim[(size_t)(row0 + r) * BB + col0 + cc] = smf[r * 129 + cc];
    }
    if (bi != bj) {
#pragma unroll 4
        for (int i = 0; i < 64; i++) {
            const int r = i * 2 + rh;
            g_sim[(size_t)(col0 + r) * BB + row0 + cc] = smf[cc * 129 + r];
        }
    }
}

// ---------------------------------------------------------------------------
// Pass 2: per-row mining + mined sums + fused final reduction (last block).
// ---------------------------------------------------------------------------
__global__ __launch_bounds__(256) void row_pass(float* __restrict__ out) {
    const int i = blockIdx.x;
    const int tid = threadIdx.x;
    const int wid = tid >> 5, lane = tid & 31;

    __shared__ float srow[BB];
    __shared__ unsigned char slab[BB];
    __shared__ float wr0[8], wr1[8];
    __shared__ int   wri[8];
    __shared__ float s_mp, s_mn;
    __shared__ int   s_last;

    *(uint4*)(slab + tid * 16) = ((const uint4*)g_lab8)[tid];
    const float* simrow = &g_sim[(size_t)i * BB];
#pragma unroll
    for (int c = 0; c < 4; c++) {
        const int j = c * 1024 + tid * 4;
        *(float4*)(srow + j) = *(const float4*)(simrow + j);
    }
    __syncthreads();

    const unsigned char li = slab[i];

    float minp = INFINITY, maxn = -INFINITY;
#pragma unroll
    for (int c = 0; c < 4; c++) {
        const int j0 = c * 1024 + tid * 4;
        const float4 v = *(const float4*)(srow + j0);
        const uint32_t lw = *(const uint32_t*)(slab + j0);
        const float sv[4] = {v.x, v.y, v.z, v.w};
#pragma unroll
        for (int e = 0; e < 4; e++) {
            const int j = j0 + e;
            const float s = sv[e];
            if (((lw >> (e * 8)) & 255u) == li) {
                if (j != i && s < 1.0f - EPS) minp = fminf(minp, s);
            } else {
                maxn = fmaxf(maxn, s);
            }
        }
    }
#pragma unroll
    for (int o = 16; o > 0; o >>= 1) {
        minp = fminf(minp, __shfl_xor_sync(0xFFFFFFFFu, minp, o));
        maxn = fmaxf(maxn, __shfl_xor_sync(0xFFFFFFFFu, maxn, o));
    }
    if (lane == 0) { wr0[wid] = minp; wr1[wid] = maxn; }
    __syncthreads();
    if (tid == 0) {
        float mp = wr0[0], mn = wr1[0];
#pragma unroll
        for (int w = 1; w < 8; w++) { mp = fminf(mp, wr0[w]); mn = fmaxf(mn, wr1[w]); }
        s_mp = mp; s_mn = mn;
    }
    __syncthreads();
    const float mp = s_mp, mn = s_mn;

    float psum = 0.0f, nsum = 0.0f;
    int flags = 0;
#pragma unroll
    for (int c = 0; c < 4; c++) {
        const int j0 = c * 1024 + tid * 4;
        const float4 v = *(const float4*)(srow + j0);
        const uint32_t lw = *(const uint32_t*)(slab + j0);
        const float sv[4] = {v.x, v.y, v.z, v.w};
#pragma unroll
        for (int e = 0; e < 4; e++) {
            const int j = j0 + e;
            const float s = sv[e];
            if (((lw >> (e * 8)) & 255u) != li) {
                if (s + MARGIN > mp) { nsum += __expf(SCALE_N * (s - THRESH)); flags |= 2; }
            } else if (j != i && s < 1.0f - EPS) {
                if (s - MARGIN < mn) { psum += __expf(-SCALE_P * (s - THRESH)); flags |= 1; }
            }
        }
    }
#pragma unroll
    for (int o = 16; o > 0; o >>= 1) {
        psum += __shfl_xor_sync(0xFFFFFFFFu, psum, o);
        nsum += __shfl_xor_sync(0xFFFFFFFFu, nsum, o);
        flags |= __shfl_xor_sync(0xFFFFFFFFu, flags, o);
    }
    if (lane == 0) { wr0[wid] = psum; wr1[wid] = nsum; wri[wid] = flags; }
    __syncthreads();

    if (tid == 0) {
        float ps = wr0[0], ns = wr1[0];
        int fl = wri[0];
#pragma unroll
        for (int w = 1; w < 8; w++) { ps += wr0[w]; ns += wr1[w]; fl |= wri[w]; }
        const bool has_row = isfinite(mp) && (mn > -INFINITY) && (fl & 1) && (fl & 2);
        float loss = 0.0f;
        if (has_row) loss = log1pf(ps) / SCALE_P + log1pf(ns) / SCALE_N;
        g_rowloss[i] = loss;
        __threadfence();
        const int old = atomicAdd(&g_ctr, 1);
        s_last = (old == BB - 1) ? 1 : 0;
    }
    __syncthreads();

    if (s_last) {
        __threadfence();
        float s = 0.0f;
        for (int k = tid; k < BB; k += 256) s += __ldcg(&g_rowloss[k]);
#pragma unroll
        for (int o = 16; o > 0; o >>= 1) s += __shfl_xor_sync(0xFFFFFFFFu, s, o);
        if (lane == 0) wr0[wid] = s;
        __syncthreads();
        if (tid == 0) {
            float t = 0.0f;
#pragma unroll
            for (int w = 0; w < 8; w++) t += wr0[w];
            out[0] = t / (float)BB;
            g_ctr = 0;   // reset for next graph replay
        }
    }
}

extern "C" void kernel_launch(void* const* d_in, const int* in_sizes, int n_in,
                              void* d_out, int out_size) {
    const float* x = (const float*)d_in[0];
    const int* labels = (const int*)d_in[1];
    float* out = (float*)d_out;

    cudaFuncSetAttribute(sim_gemm_imma, cudaFuncAttributeMaxDynamicSharedMemorySize,
                         SMEM_DYN);

    convert_q8<<<(BB * DD / 8) / 256, 256>>>((const float4*)x, labels);
    sim_gemm_imma<<<NCTA, 256, SMEM_DYN>>>();
    row_pass<<<BB, 256>>>(out);
}

// round 15
// speedup vs baseline: 1.7658x; 1.7658x over previous
#include <cuda_runtime.h>
#include <cuda_bf16.h>
#include <math.h>
#include <stdint.h>

#define BB 4096
#define DD 1024

#define THRESH   0.5f
#define MARGIN   0.1f
#define SCALE_P  2.0f
#define SCALE_N  40.0f
#define EPS      1e-5f

// Static scratch (no allocs).
__device__ float g_sim[(size_t)BB * BB];
__device__ __align__(16) __nv_bfloat16 g_xb[(size_t)BB * DD];
__device__ __align__(16) unsigned char g_lab8[BB];
__device__ float g_pmin[(size_t)BB * 32];   // per (row, coltile) min valid pos
__device__ float g_pmax[(size_t)BB * 32];   // per (row, coltile) max neg
__device__ float g_rowloss[BB];
__device__ int g_ctr = 0;

// ---------------------------------------------------------------------------
// Helpers
// ---------------------------------------------------------------------------
__device__ __forceinline__ uint32_t smem_u32(const void* p) {
    uint32_t a;
    asm("{ .reg .u64 t; cvta.to.shared.u64 t, %1; cvt.u32.u64 %0, t; }"
        : "=r"(a) : "l"(p));
    return a;
}
#define CP_ASYNC16(dst, src) \
    asm volatile("cp.async.cg.shared.global [%0], [%1], 16;" :: "r"(dst), "l"(src))
#define CP_COMMIT() asm volatile("cp.async.commit_group;" ::: "memory")
#define CP_WAIT(n)  asm volatile("cp.async.wait_group %0;" :: "n"(n) : "memory")

__device__ __forceinline__ void ldmatrix_x4(uint32_t& r0, uint32_t& r1,
                                            uint32_t& r2, uint32_t& r3,
                                            uint32_t addr) {
    asm volatile("ldmatrix.sync.aligned.m8n8.x4.shared.b16 {%0,%1,%2,%3}, [%4];"
                 : "=r"(r0), "=r"(r1), "=r"(r2), "=r"(r3) : "r"(addr));
}
__device__ __forceinline__ void mma_bf16(float& c0, float& c1, float& c2, float& c3,
                                         uint32_t a0, uint32_t a1, uint32_t a2,
                                         uint32_t a3, uint32_t b0, uint32_t b1) {
    asm volatile(
        "mma.sync.aligned.m16n8k16.row.col.f32.bf16.bf16.f32 "
        "{%0,%1,%2,%3}, {%4,%5,%6,%7}, {%8,%9}, {%0,%1,%2,%3};"
        : "+f"(c0), "+f"(c1), "+f"(c2), "+f"(c3)
        : "r"(a0), "r"(a1), "r"(a2), "r"(a3), "r"(b0), "r"(b1));
}

// ---------------------------------------------------------------------------
// Pass 0: f32 -> bf16 conversion of x + labels -> u8 (block 0).
// ---------------------------------------------------------------------------
__global__ __launch_bounds__(256) void convert_bf16(const float4* __restrict__ x,
                                                    const int* __restrict__ labels) {
#pragma unroll
    for (int q = 0; q < 2; q++) {
        const int i = blockIdx.x * 512 + q * 256 + threadIdx.x;
        float4 v = x[i];
        __nv_bfloat162 a = __floats2bfloat162_rn(v.x, v.y);
        __nv_bfloat162 b = __floats2bfloat162_rn(v.z, v.w);
        uint32_t pa, pb;
        memcpy(&pa, &a, 4); memcpy(&pb, &b, 4);
        ((uint2*)g_xb)[i] = make_uint2(pa, pb);
    }
    if (blockIdx.x == 0) {
        const int t = threadIdx.x;
#pragma unroll
        for (int k = 0; k < 4; k++) {
            int4 lv = *(const int4*)(labels + t * 16 + k * 4);
            uchar4 u;
            u.x = (unsigned char)lv.x; u.y = (unsigned char)lv.y;
            u.z = (unsigned char)lv.z; u.w = (unsigned char)lv.w;
            *(uchar4*)(g_lab8 + t * 16 + k * 4) = u;
        }
    }
}

// ---------------------------------------------------------------------------
// Pass 1: bf16 mma.sync symmetric GEMM (R9 config) + fused mining pass 1.
// Triangular 528-CTA launch, tile 128x128, 8 warps (2x4), warp tile 64x32,
// K-chunk 64, 2-stage cp.async. Epilogue stores sim and per-tile
// min_pos/max_neg partials (direct rows + mirror rows).
// ---------------------------------------------------------------------------
#define KC 64
#define ROWB 144                    // 64*2 + 16 pad
#define TILE_B (128 * ROWB)         // 18432 B per A or B stage
#define OFF_B  (2 * TILE_B)
#define SMEM_DYN (4 * TILE_B)       // 73728 B
#define NT 32
#define NCTA (NT * (NT + 1) / 2)    // 528

__global__ __launch_bounds__(256, 2) void sim_gemm_mma() {
    const int idx = blockIdx.x;
    int bi = (int)((65.0f - sqrtf(4225.0f - 8.0f * (float)idx)) * 0.5f);
    while ((bi + 1) * (65 - (bi + 1)) / 2 <= idx) bi++;
    while (bi * (65 - bi) / 2 > idx) bi--;
    const int bj = bi + (idx - bi * (65 - bi) / 2);

    extern __shared__ __align__(16) char smem[];
    __shared__ unsigned char labR[128], labC[128];
    const uint32_t sA = smem_u32(smem);
    const uint32_t sB = sA + OFF_B;

    const int tid = threadIdx.x;
    const int wid = tid >> 5, lane = tid & 31;
    const int warp_m = wid >> 2;
    const int warp_n = wid & 3;
    const int row0 = bi * 128, col0 = bj * 128;

    if (tid < 128) labR[tid] = g_lab8[row0 + tid];
    else           labC[tid - 128] = g_lab8[col0 + tid - 128];

    uint32_t dstA[4];
    const __nv_bfloat16 *srcA[4], *srcB[4];
#pragma unroll
    for (int p = 0; p < 4; p++) {
        const int ii = p * 256 + tid;
        const int r = ii >> 3, kc = ii & 7;
        dstA[p] = (uint32_t)(r * ROWB + kc * 16);
        srcA[p] = g_xb + (size_t)(row0 + r) * DD + kc * 8;
        srcB[p] = g_xb + (size_t)(col0 + r) * DD + kc * 8;
    }

    float acc[4][4][4];
#pragma unroll
    for (int a = 0; a < 4; a++)
#pragma unroll
        for (int b = 0; b < 4; b++)
#pragma unroll
            for (int c = 0; c < 4; c++) acc[a][b][c] = 0.0f;

    const int a_mrow = warp_m * 64 + (lane & 7) + ((lane >> 3) & 1) * 8;
    const int a_kcol = (lane >> 4) << 3;
    const int b_nrow = warp_n * 32 + (lane & 7) + ((lane >> 4) << 3);
    const int b_kcol = ((lane >> 3) & 1) << 3;

#pragma unroll
    for (int p = 0; p < 4; p++) {
        CP_ASYNC16(sA + dstA[p], srcA[p]);
        CP_ASYNC16(sB + dstA[p], srcB[p]);
    }
    CP_COMMIT();

    for (int ck = 0; ck < DD / KC; ck++) {
        CP_WAIT(0);
        __syncthreads();

        if (ck + 1 < DD / KC) {
            const uint32_t st = ((ck + 1) & 1) * TILE_B;
            const int k0 = (ck + 1) * KC;
#pragma unroll
            for (int p = 0; p < 4; p++) {
                CP_ASYNC16(sA + st + dstA[p], srcA[p] + k0);
                CP_ASYNC16(sB + st + dstA[p], srcB[p] + k0);
            }
            CP_COMMIT();
        }

        const uint32_t stA = sA + (ck & 1) * TILE_B;
        const uint32_t stB = sB + (ck & 1) * TILE_B;

#pragma unroll
        for (int ks = 0; ks < KC / 16; ks++) {
            uint32_t af[4][4], bf[2][4];
#pragma unroll
            for (int mf = 0; mf < 4; mf++)
                ldmatrix_x4(af[mf][0], af[mf][1], af[mf][2], af[mf][3],
                            stA + (uint32_t)((a_mrow + mf * 16) * ROWB
                                             + (ks * 16 + a_kcol) * 2));
#pragma unroll
            for (int nfp = 0; nfp < 2; nfp++)
                ldmatrix_x4(bf[nfp][0], bf[nfp][1], bf[nfp][2], bf[nfp][3],
                            stB + (uint32_t)((b_nrow + nfp * 16) * ROWB
                                             + (ks * 16 + b_kcol) * 2));
#pragma unroll
            for (int mf = 0; mf < 4; mf++)
#pragma unroll
                for (int nf = 0; nf < 4; nf++) {
                    const uint32_t b0 = bf[nf >> 1][(nf & 1) * 2];
                    const uint32_t b1 = bf[nf >> 1][(nf & 1) * 2 + 1];
                    mma_bf16(acc[mf][nf][0], acc[mf][nf][1],
                             acc[mf][nf][2], acc[mf][nf][3],
                             af[mf][0], af[mf][1], af[mf][2], af[mf][3], b0, b1);
                }
        }
    }
    __syncthreads();

    // Epilogue: regs -> padded SMEM (stride 129).
    float* smf = (float*)smem;
    {
        const int r_lo = warp_m * 64 + (lane >> 2);
        const int c_lo = warp_n * 32 + (lane & 3) * 2;
#pragma unroll
        for (int mf = 0; mf < 4; mf++)
#pragma unroll
            for (int nf = 0; nf < 4; nf++) {
                const int r = r_lo + mf * 16;
                const int c = c_lo + nf * 8;
                smf[r * 129 + c]           = acc[mf][nf][0];
                smf[r * 129 + c + 1]       = acc[mf][nf][1];
                smf[(r + 8) * 129 + c]     = acc[mf][nf][2];
                smf[(r + 8) * 129 + c + 1] = acc[mf][nf][3];
            }
    }
    __syncthreads();

    const int cc = tid & 127;
    const int rh = tid >> 7;
#pragma unroll 4
    for (int i = 0; i < 64; i++) {
        const int r = i * 2 + rh;
        g_sim[(size_t)(row0 + r) * BB + col0 + cc] = smf[r * 129 + cc];
    }
    if (bi != bj) {
#pragma unroll 4
        for (int i = 0; i < 64; i++) {
            const int r = i * 2 + rh;
            g_sim[(size_t)(col0 + r) * BB + row0 + cc] = smf[cc * 129 + r];
        }
    }

    // Fused mining pass 1: per-row min_pos / max_neg over this tile.
    if (tid < 128) {
        const int r = tid;
        const int gi = row0 + r;
        const unsigned char li = labR[r];
        float mp = INFINITY, mn = -INFINITY;
#pragma unroll 4
        for (int c = 0; c < 128; c++) {
            const float s = smf[r * 129 + c];
            if (labC[c] != li) {
                mn = fmaxf(mn, s);
            } else if (gi != col0 + c && s < 1.0f - EPS) {
                mp = fminf(mp, s);
            }
        }
        g_pmin[(size_t)gi * 32 + bj] = mp;
        g_pmax[(size_t)gi * 32 + bj] = mn;
    } else if (bi != bj) {
        const int j = tid - 128;
        const int gj = col0 + j;
        const unsigned char lj = labC[j];
        float mp = INFINITY, mn = -INFINITY;
#pragma unroll 4
        for (int rr = 0; rr < 128; rr++) {
            const float s = smf[rr * 129 + j];
            if (labR[rr] != lj) {
                mn = fmaxf(mn, s);
            } else if (gj != row0 + rr && s < 1.0f - EPS) {
                mp = fminf(mp, s);
            }
        }
        g_pmin[(size_t)gj * 32 + bi] = mp;
        g_pmax[(size_t)gj * 32 + bi] = mn;
    }
}

// ---------------------------------------------------------------------------
// Pass 2: reduce partials + single streaming sweep for mined sums,
// fused final reduction in the last block.
// ---------------------------------------------------------------------------
__global__ __launch_bounds__(256) void row_pass(float* __restrict__ out) {
    const int i = blockIdx.x;
    const int tid = threadIdx.x;
    const int wid = tid >> 5, lane = tid & 31;

    __shared__ unsigned char slab[BB];
    __shared__ float wr0[8], wr1[8];
    __shared__ int   wri[8];
    __shared__ float s_mp, s_mn;
    __shared__ int   s_last;

    *(uint4*)(slab + tid * 16) = ((const uint4*)g_lab8)[tid];

    // Reduce 32 tile-partials (warp 0 only).
    if (wid == 0) {
        float mp = g_pmin[(size_t)i * 32 + lane];
        float mn = g_pmax[(size_t)i * 32 + lane];
#pragma unroll
        for (int o = 16; o > 0; o >>= 1) {
            mp = fminf(mp, __shfl_xor_sync(0xFFFFFFFFu, mp, o));
            mn = fmaxf(mn, __shfl_xor_sync(0xFFFFFFFFu, mn, o));
        }
        if (lane == 0) { s_mp = mp; s_mn = mn; }
    }
    __syncthreads();
    const float mp = s_mp, mn = s_mn;
    const unsigned char li = slab[i];

    // Single streaming sweep: mined sums (row read once from DRAM, no reuse).
    const float* simrow = &g_sim[(size_t)i * BB];
    float psum = 0.0f, nsum = 0.0f;
    int flags = 0;
#pragma unroll
    for (int c = 0; c < 4; c++) {
        const int j0 = c * 1024 + tid * 4;
        const float4 v = __ldcs((const float4*)(simrow + j0));
        const uint32_t lw = *(const uint32_t*)(slab + j0);
        const float sv[4] = {v.x, v.y, v.z, v.w};
#pragma unroll
        for (int e = 0; e < 4; e++) {
            const int j = j0 + e;
            const float s = sv[e];
            if (((lw >> (e * 8)) & 255u) != li) {
                if (s + MARGIN > mp) { nsum += __expf(SCALE_N * (s - THRESH)); flags |= 2; }
            } else if (j != i && s < 1.0f - EPS) {
                if (s - MARGIN < mn) { psum += __expf(-SCALE_P * (s - THRESH)); flags |= 1; }
            }
        }
    }
#pragma unroll
    for (int o = 16; o > 0; o >>= 1) {
        psum += __shfl_xor_sync(0xFFFFFFFFu, psum, o);
        nsum += __shfl_xor_sync(0xFFFFFFFFu, nsum, o);
        flags |= __shfl_xor_sync(0xFFFFFFFFu, flags, o);
    }
    if (lane == 0) { wr0[wid] = psum; wr1[wid] = nsum; wri[wid] = flags; }
    __syncthreads();

    if (tid == 0) {
        float ps = wr0[0], ns = wr1[0];
        int fl = wri[0];
#pragma unroll
        for (int w = 1; w < 8; w++) { ps += wr0[w]; ns += wr1[w]; fl |= wri[w]; }
        const bool has_row = isfinite(mp) && (mn > -INFINITY) && (fl & 1) && (fl & 2);
        float loss = 0.0f;
        if (has_row) loss = log1pf(ps) / SCALE_P + log1pf(ns) / SCALE_N;
        g_rowloss[i] = loss;
        __threadfence();
        const int old = atomicAdd(&g_ctr, 1);
        s_last = (old == BB - 1) ? 1 : 0;
    }
    __syncthreads();

    if (s_last) {
        __threadfence();
        float s = 0.0f;
        for (int k = tid; k < BB; k += 256) s += __ldcg(&g_rowloss[k]);
#pragma unroll
        for (int o = 16; o > 0; o >>= 1) s += __shfl_xor_sync(0xFFFFFFFFu, s, o);
        if (lane == 0) wr0[wid] = s;
        __syncthreads();
        if (tid == 0) {
            float t = 0.0f;
#pragma unroll
            for (int w = 0; w < 8; w++) t += wr0[w];
            out[0] = t / (float)BB;
            g_ctr = 0;   // reset for next graph replay
        }
    }
}

extern "C" void kernel_launch(void* const* d_in, const int* in_sizes, int n_in,
                              void* d_out, int out_size) {
    const float* x = (const float*)d_in[0];
    const int* labels = (const int*)d_in[1];
    float* out = (float*)d_out;

    cudaFuncSetAttribute(sim_gemm_mma, cudaFuncAttributeMaxDynamicSharedMemorySize,
                         SMEM_DYN);

    convert_bf16<<<(BB * DD / 4) / 512, 256>>>((const float4*)x, labels);
    sim_gemm_mma<<<NCTA, 256, SMEM_DYN>>>();
    row_pass<<<BB, 256>>>(out);
}